// round 17
// baseline (speedup 1.0000x reference)
#include <cuda_runtime.h>
#include <cstdint>

// 3x3 median blur, zero padding, fp32 NCHW (8,3,512,512).
// CTA-pipelined kernel: 128-thread CTA covers a 128x16 output tile and walks
// 4 consecutive y-tiles. Input for tile i+1 is staged into shared memory via
// cp.async (fire-and-forget) WHILE tile i computes from the other buffer ->
// global-load latency (L2 ~250cyc) is structurally hidden; compute reads
// smem at LDS latency (29cyc), covered by the 6-column/4-pixel ILP of the
// R9 median network (16 min/max ops per pixel).

#define SW   136   // floats per smem row (128 tile + 4+4 halo, 16B aligned)
#define NROW 18    // input rows per tile (16 outputs + 2 halo)
#define NCHUNK (NROW * 34)   // 16B chunks per tile (34 float4 per row)

__device__ __forceinline__ float med3(float a, float b, float c) {
    return fmaxf(fminf(a, b), fminf(fmaxf(a, b), c));
}

__device__ __forceinline__ void triples(const float r[6], const float mn[6],
                                        const float mx[6],
                                        float lo[6], float mi[6], float hi[6]) {
    #pragma unroll
    for (int j = 0; j < 6; ++j) {
        const float u = fmaxf(r[j], mn[j]);
        lo[j] = fminf(r[j], mn[j]);
        mi[j] = fminf(u, mx[j]);
        hi[j] = fmaxf(u, mx[j]);
    }
}

__device__ __forceinline__ void merge_row(const float lo[6], const float mi[6],
                                          const float hi[6], float* dst) {
    const float m12 = fmaxf(lo[1], lo[2]);
    const float m34 = fmaxf(lo[3], lo[4]);
    const float A0 = fmaxf(lo[0], m12);
    const float A1 = fmaxf(m12, lo[3]);
    const float A2 = fmaxf(lo[2], m34);
    const float A3 = fmaxf(m34, lo[5]);
    const float n12 = fminf(hi[1], hi[2]);
    const float n34 = fminf(hi[3], hi[4]);
    const float C0 = fminf(hi[0], n12);
    const float C1 = fminf(n12, hi[3]);
    const float C2 = fminf(hi[2], n34);
    const float C3 = fminf(n34, hi[5]);
    const float p12 = fminf(mi[1], mi[2]), q12 = fmaxf(mi[1], mi[2]);
    const float p34 = fminf(mi[3], mi[4]), q34 = fmaxf(mi[3], mi[4]);
    const float B0 = fmaxf(p12, fminf(mi[0], q12));
    const float B1 = fmaxf(p12, fminf(mi[3], q12));
    const float B2 = fmaxf(p34, fminf(mi[2], q34));
    const float B3 = fmaxf(p34, fminf(mi[5], q34));
    float4 o;
    o.x = med3(A0, B0, C0);
    o.y = med3(A1, B1, C1);
    o.z = med3(A2, B2, C2);
    o.w = med3(A3, B3, C3);
    *reinterpret_cast<float4*>(dst) = o;
}

// Stage one 18-row input tile (rows Y-1..Y+16, cols xbase-4..xbase+131)
// into smem buffer via cp.async; OOB chunks are STS-zeroed (uniform padding).
__device__ __forceinline__ void prefetch_tile(float* buf,
                                              const float* __restrict__ p,
                                              int xbase, int Y, int tid) {
    #pragma unroll
    for (int i = tid; i < NCHUNK; i += 128) {
        const int r = i / 34;
        const int c = i % 34;
        const int yg = Y - 1 + r;
        const int xg = xbase - 4 + c * 4;
        float* dst = buf + r * SW + c * 4;
        if ((unsigned)yg < 512u && (unsigned)xg < 512u) {   // xg%4==0 => full chunk in-bounds
            const float* src = p + yg * 512 + xg;
            uint32_t daddr = (uint32_t)__cvta_generic_to_shared(dst);
            asm volatile("cp.async.ca.shared.global [%0], [%1], 16;"
                         :: "r"(daddr), "l"(src) : "memory");
        } else {
            *reinterpret_cast<float4*>(dst) = make_float4(0.f, 0.f, 0.f, 0.f);
        }
    }
    asm volatile("cp.async.commit_group;" ::: "memory");
}

// Compute the 128x16 tile from a staged smem buffer (R9 body, LDS reads).
__device__ __forceinline__ void compute_tile(const float* buf,
                                             float* __restrict__ outp,
                                             int x0, int Y, int tx, int ty) {
    float v[6][6];
    #pragma unroll
    for (int i = 0; i < 6; ++i) {
        const float* srow = buf + (ty * 4 + i) * SW + tx * 4;
        const float4 a = *reinterpret_cast<const float4*>(srow);      // x0-4..x0-1
        const float4 b = *reinterpret_cast<const float4*>(srow + 4);  // x0..x0+3
        const float4 c = *reinterpret_cast<const float4*>(srow + 8);  // x0+4..
        v[i][0] = a.w;
        v[i][1] = b.x; v[i][2] = b.y; v[i][3] = b.z; v[i][4] = b.w;
        v[i][5] = c.x;
    }

    const int y0 = Y + ty * 4;
    float* __restrict__ orow = outp + y0 * 512 + x0;
    float t_lo[6], t_mi[6], t_hi[6];
    float mn[6], mx[6];

    #pragma unroll
    for (int j = 0; j < 6; ++j) {
        mn[j] = fminf(v[1][j], v[2][j]);
        mx[j] = fmaxf(v[1][j], v[2][j]);
    }
    triples(v[0], mn, mx, t_lo, t_mi, t_hi);
    merge_row(t_lo, t_mi, t_hi, orow);
    triples(v[3], mn, mx, t_lo, t_mi, t_hi);
    merge_row(t_lo, t_mi, t_hi, orow + 512);

    #pragma unroll
    for (int j = 0; j < 6; ++j) {
        mn[j] = fminf(v[3][j], v[4][j]);
        mx[j] = fmaxf(v[3][j], v[4][j]);
    }
    triples(v[2], mn, mx, t_lo, t_mi, t_hi);
    merge_row(t_lo, t_mi, t_hi, orow + 2 * 512);
    triples(v[5], mn, mx, t_lo, t_mi, t_hi);
    merge_row(t_lo, t_mi, t_hi, orow + 3 * 512);
}

__global__ __launch_bounds__(128, 8)
void MedianBlur_34505767256654_kernel(const float* __restrict__ in,
                                      float* __restrict__ out) {
    __shared__ float smem[2][NROW * SW];

    const int tid = threadIdx.y * 32 + threadIdx.x;
    const int tx = threadIdx.x;
    const int ty = threadIdx.y;

    const int xbase = blockIdx.x * 128;            // x-slab
    const int x0 = xbase + tx * 4;
    const int base = blockIdx.z * (512 * 512);     // plane
    const float* __restrict__ p = in + base;
    float* __restrict__ o = out + base;

    // This CTA walks 4 consecutive 16-row y-tiles.
    const int Y0 = blockIdx.y * 64;

    prefetch_tile(smem[0], p, xbase, Y0, tid);

    #pragma unroll
    for (int it = 0; it < 4; ++it) {
        const int Y = Y0 + it * 16;
        if (it < 3) {
            prefetch_tile(smem[(it + 1) & 1], p, xbase, Y + 16, tid);
            asm volatile("cp.async.wait_group 1;" ::: "memory");
        } else {
            asm volatile("cp.async.wait_group 0;" ::: "memory");
        }
        __syncthreads();                  // buffer it&1 fully staged
        compute_tile(smem[it & 1], o, x0, Y, tx, ty);
        __syncthreads();                  // done reading before it's refilled
    }
}

extern "C" void kernel_launch(void* const* d_in, const int* in_sizes, int n_in,
                              void* d_out, int out_size) {
    (void)in_sizes; (void)n_in; (void)out_size;
    const float* x = (const float*)d_in[0];
    float* out = (float*)d_out;

    dim3 block(32, 4, 1);                 // 128 threads
    dim3 grid(4, 8, 24);                  // x-slabs, 64-row y-bands, planes
    MedianBlur_34505767256654_kernel<<<grid, block>>>(x, out);
}